// round 3
// baseline (speedup 1.0000x reference)
#include <cuda_runtime.h>
#include <cuda_bf16.h>
#include <cstdint>

#define DINL __device__ __forceinline__

// ======================= helpers =======================
DINL uint32_t smem_u32(const void* p) {
    uint32_t a;
    asm("{ .reg .u64 t; cvta.to.shared.u64 t, %1; cvt.u32.u64 %0, t; }" : "=r"(a) : "l"(p));
    return a;
}
DINL void ldsm_x4(uint32_t r[4], uint32_t addr) {
    asm volatile("ldmatrix.sync.aligned.m8n8.x4.shared.b16 {%0,%1,%2,%3}, [%4];"
        : "=r"(r[0]), "=r"(r[1]), "=r"(r[2]), "=r"(r[3]) : "r"(addr));
}
DINL void mma_bf16(float c[4], const uint32_t a[4], const uint32_t b[2]) {
    asm volatile("mma.sync.aligned.m16n8k16.row.col.f32.bf16.bf16.f32 "
        "{%0,%1,%2,%3}, {%4,%5,%6,%7}, {%8,%9}, {%0,%1,%2,%3};"
        : "+f"(c[0]), "+f"(c[1]), "+f"(c[2]), "+f"(c[3])
        : "r"(a[0]), "r"(a[1]), "r"(a[2]), "r"(a[3]), "r"(b[0]), "r"(b[1]));
}
#define STS32(a, v) asm volatile("st.shared.b32 [%0], %1;" :: "r"(a), "r"(v) : "memory")
#define STS64(a, v) asm volatile("st.shared.b64 [%0], %1;" :: "r"(a), "l"(v) : "memory")

DINL uint32_t pack2(float a, float b) {
    return ((uint32_t)__bfloat16_as_ushort(__float2bfloat16(b)) << 16)
         |  (uint32_t)__bfloat16_as_ushort(__float2bfloat16(a));
}
DINL uint64_t pack4(float a, float b, float c, float d) {
    return ((uint64_t)pack2(c, d) << 32) | (uint64_t)pack2(a, b);
}
DINL float rlo(float f) { return f - __bfloat162float(__float2bfloat16(f)); }

// ======================= SMEM layout (per CTA: 64-row tile) =======================
// A hi [0,16K) | A lo [16K,32K) | h hi [32K,48K) | h lo [48K,64K)
static constexpr int A_HI = 0;
static constexpr int A_LO = 16384;
static constexpr int H_HI = 32768;
static constexpr int H_LO = 49152;
static constexpr int SMEM_TOTAL = 65536;

// ======================= device globals =======================
// plain [n][k] bf16 images: W1eff hi, W1eff lo, W2 hi, W2 lo (16384 bf16 each)
__device__ __align__(16) unsigned char g_wimg[4 * 32768];
__device__ int g_idx64;

// ======================= prologue =======================
__global__ void prep_kernel(const float* __restrict__ W1, const float* __restrict__ W2,
                            const void* __restrict__ nbr_raw) {
    int n = blockIdx.x;    // output channel
    int k = threadIdx.x;   // reduction index
    float w1e = W1[k * 128 + n] + W1[(k + 128) * 128 + n];  // fold concat
    float w2v = W2[k * 128 + n];
    __nv_bfloat16* img = (__nv_bfloat16*)g_wimg;
    __nv_bfloat16 h1 = __float2bfloat16(w1e);
    __nv_bfloat16 l1 = __float2bfloat16(w1e - __bfloat162float(h1));
    __nv_bfloat16 h2 = __float2bfloat16(w2v);
    __nv_bfloat16 l2 = __float2bfloat16(w2v - __bfloat162float(h2));
    img[0 * 16384 + n * 128 + k] = h1;
    img[1 * 16384 + n * 128 + k] = l1;
    img[2 * 16384 + n * 128 + k] = h2;
    img[3 * 16384 + n * 128 + k] = l2;

    if (blockIdx.x == 0 && threadIdx.x == 0) {
        const unsigned* w = (const unsigned*)nbr_raw;
        int is64 = 1;
        for (int i = 0; i < 64; i++)
            if (w[2 * i + 1] != 0u) { is64 = 0; break; }
        g_idx64 = is64;
    }
}

// ======================= gather: 8 rows per warp into swizzled A hi/lo =======================
DINL void gather_tile(const float* __restrict__ x, const long long* n64, const int* n32,
                      int use64, int E, int rowbase, int wid, int lane,
                      uint32_t AHIa, uint32_t ALOa) {
    long long myidx = 0;
    if (lane < 8) {
        int gr = rowbase + wid * 8 + lane;
        if (gr < E) myidx = use64 ? n64[gr] : (long long)n32[gr];
    }
    const uint32_t within = (uint32_t)((lane & 1) << 3);
    const int cstore = lane >> 1;
#pragma unroll
    for (int r = 0; r < 8; r++) {
        long long gi = __shfl_sync(0xffffffffu, myidx, r);
        const float4 v = *(const float4*)(x + gi * 128 + (lane << 2));
        int row = wid * 8 + r;
        uint32_t off = (uint32_t)(row * 256) + (uint32_t)((cstore ^ (row & 7)) << 4) + within;
        STS64(AHIa + off, pack4(v.x, v.y, v.z, v.w));
        STS64(ALOa + off, pack4(rlo(v.x), rlo(v.y), rlo(v.z), rlo(v.w)));
    }
}

// ======================= main kernel =======================
__global__ void __launch_bounds__(256, 3)
gs_kernel(const float* __restrict__ x, const void* __restrict__ nbr_raw,
          const float* __restrict__ b1, const float* __restrict__ b2,
          float* __restrict__ out, int E) {
    extern __shared__ unsigned char sm[];
    const uint32_t sb = smem_u32(sm);
    const int tid = threadIdx.x, wid = tid >> 5, lane = tid & 31;

    // ---- persistent B fragments: both GEMMs, hi+lo, for this warp's 16 cols ----
    // fragment reg (n8, ks, j): word at n = n8*8 + lane/4, k = ks*16 + j*8 + (lane%3)*2
    uint32_t B1h[2][8][2], B1l[2][8][2], B2h[2][8][2], B2l[2][8][2];
    {
        const uint32_t* w32 = (const uint32_t*)g_wimg;
        const int lrow = lane >> 2, lcol = lane & 3;
#pragma unroll
        for (int nc = 0; nc < 2; nc++) {
            const int nb = (wid * 16 + nc * 8 + lrow) * 64;
#pragma unroll
            for (int ks = 0; ks < 8; ks++)
#pragma unroll
                for (int j = 0; j < 2; j++) {
                    const int wi = nb + ks * 8 + j * 4 + lcol;
                    B1h[nc][ks][j] = w32[wi];
                    B1l[nc][ks][j] = w32[8192 + wi];
                    B2h[nc][ks][j] = w32[16384 + wi];
                    B2l[nc][ks][j] = w32[24576 + wi];
                }
        }
    }
    // biases for this lane's two columns per nc
    float b1r[2][2], b2r[2][2];
#pragma unroll
    for (int nc = 0; nc < 2; nc++) {
        const int n0 = wid * 16 + nc * 8 + (lane & 3) * 2;
        b1r[nc][0] = b1[n0]; b1r[nc][1] = b1[n0 + 1];
        b2r[nc][0] = b2[n0]; b2r[nc][1] = b2[n0 + 1];
    }

    // ldmatrix lane addressing (A / h fragments)
    const int li = lane & 7, lg = lane >> 3;
    const int arow = ((lg & 1) << 3) + li;
    const int akh = lg >> 1;
    const uint32_t arowoff = (uint32_t)arow * 256u;
    const int arx = arow & 7;

    const int use64 = g_idx64;
    const long long* nbr64 = (const long long*)nbr_raw;
    const int* nbr32 = (const int*)nbr_raw;

    const int ntiles = (E + 63) >> 6;
    const int stride = gridDim.x;

    int tile = blockIdx.x;
    if (tile < ntiles)
        gather_tile(x, nbr64, nbr32, use64, E, tile << 6, wid, lane, sb + A_HI, sb + A_LO);
    __syncthreads();

    for (; tile < ntiles; tile += stride) {
        const int rowbase = tile << 6;

        // ================= GEMM1: h = relu(A @ W1eff + b1) =================
#pragma unroll 1
        for (int mt = 0; mt < 4; mt++) {
            float acc[2][4] = {{0.f,0.f,0.f,0.f},{0.f,0.f,0.f,0.f}};
            const uint32_t mtoff = (uint32_t)(mt * 4096);
#pragma unroll
            for (int kh = 0; kh < 2; kh++) {
                uint32_t Ah[4][4], Al[4][4];
#pragma unroll
                for (int k4 = 0; k4 < 4; k4++) {
                    const int ks = kh * 4 + k4;
                    const uint32_t c = (uint32_t)((((ks << 1) + akh) ^ arx) << 4);
                    ldsm_x4(Ah[k4], sb + A_HI + mtoff + arowoff + c);
                    ldsm_x4(Al[k4], sb + A_LO + mtoff + arowoff + c);
                }
#pragma unroll
                for (int k4 = 0; k4 < 4; k4++) {
                    const int ks = kh * 4 + k4;
                    mma_bf16(acc[0], Ah[k4], B1h[0][ks]);
                    mma_bf16(acc[1], Ah[k4], B1h[1][ks]);
                }
#pragma unroll
                for (int k4 = 0; k4 < 4; k4++) {
                    const int ks = kh * 4 + k4;
                    mma_bf16(acc[0], Ah[k4], B1l[0][ks]);
                    mma_bf16(acc[1], Ah[k4], B1l[1][ks]);
                    mma_bf16(acc[0], Al[k4], B1h[0][ks]);
                    mma_bf16(acc[1], Al[k4], B1h[1][ks]);
                }
            }
            // epilogue -> h (hi/lo, swizzled), conflict-free banks
            const int r0 = mt * 16 + (lane >> 2), r1 = r0 + 8;
#pragma unroll
            for (int nc = 0; nc < 2; nc++) {
                const float f0 = fmaxf(acc[nc][0] + b1r[nc][0], 0.f);
                const float f1 = fmaxf(acc[nc][1] + b1r[nc][1], 0.f);
                const float f2 = fmaxf(acc[nc][2] + b1r[nc][0], 0.f);
                const float f3 = fmaxf(acc[nc][3] + b1r[nc][1], 0.f);
                const int col = wid * 16 + nc * 8 + (lane & 3) * 2;
                const uint32_t a0 = (uint32_t)(r0 * 256 + (((col >> 3) ^ (r0 & 7)) << 4) + ((col & 7) << 1));
                const uint32_t a1 = (uint32_t)(r1 * 256 + (((col >> 3) ^ (r1 & 7)) << 4) + ((col & 7) << 1));
                STS32(sb + H_HI + a0, pack2(f0, f1));
                STS32(sb + H_LO + a0, pack2(rlo(f0), rlo(f1)));
                STS32(sb + H_HI + a1, pack2(f2, f3));
                STS32(sb + H_LO + a1, pack2(rlo(f2), rlo(f3)));
            }
        }
        __syncthreads();   // h ready; all A reads done

        // prefetch next tile's gather into A (overlaps GEMM2)
        const int nt = tile + stride;
        if (nt < ntiles)
            gather_tile(x, nbr64, nbr32, use64, E, nt << 6, wid, lane, sb + A_HI, sb + A_LO);

        // ================= GEMM2: y = h @ W2 + b2 =================
#pragma unroll 1
        for (int mt = 0; mt < 4; mt++) {
            float acc[2][4] = {{0.f,0.f,0.f,0.f},{0.f,0.f,0.f,0.f}};
            const uint32_t mtoff = (uint32_t)(mt * 4096);
#pragma unroll
            for (int kh = 0; kh < 2; kh++) {
                uint32_t Ah[4][4], Al[4][4];
#pragma unroll
                for (int k4 = 0; k4 < 4; k4++) {
                    const int ks = kh * 4 + k4;
                    const uint32_t c = (uint32_t)((((ks << 1) + akh) ^ arx) << 4);
                    ldsm_x4(Ah[k4], sb + H_HI + mtoff + arowoff + c);
                    ldsm_x4(Al[k4], sb + H_LO + mtoff + arowoff + c);
                }
#pragma unroll
                for (int k4 = 0; k4 < 4; k4++) {
                    const int ks = kh * 4 + k4;
                    mma_bf16(acc[0], Ah[k4], B2h[0][ks]);
                    mma_bf16(acc[1], Ah[k4], B2h[1][ks]);
                }
#pragma unroll
                for (int k4 = 0; k4 < 4; k4++) {
                    const int ks = kh * 4 + k4;
                    mma_bf16(acc[0], Ah[k4], B2l[0][ks]);
                    mma_bf16(acc[1], Ah[k4], B2l[1][ks]);
                    mma_bf16(acc[0], Al[k4], B2h[0][ks]);
                    mma_bf16(acc[1], Al[k4], B2h[1][ks]);
                }
            }
            // epilogue -> global
            const int rg0 = rowbase + mt * 16 + (lane >> 2), rg1 = rg0 + 8;
#pragma unroll
            for (int nc = 0; nc < 2; nc++) {
                const int col = wid * 16 + nc * 8 + (lane & 3) * 2;
                if (rg0 < E)
                    *(float2*)(out + (size_t)rg0 * 128 + col) =
                        make_float2(acc[nc][0] + b2r[nc][0], acc[nc][1] + b2r[nc][1]);
                if (rg1 < E)
                    *(float2*)(out + (size_t)rg1 * 128 + col) =
                        make_float2(acc[nc][2] + b2r[nc][0], acc[nc][3] + b2r[nc][1]);
            }
        }
        __syncthreads();   // h free for next GEMM1; A fully gathered
    }
}

// ======================= launch =======================
extern "C" void kernel_launch(void* const* d_in, const int* in_sizes, int n_in,
                              void* d_out, int out_size) {
    const float* x  = (const float*)d_in[0];
    const void*  nb = d_in[1];
    const float* W1 = (const float*)d_in[2];
    const float* b1 = (const float*)d_in[3];
    const float* W2 = (const float*)d_in[4];
    const float* b2 = (const float*)d_in[5];
    float* out = (float*)d_out;
    const int E = in_sizes[1];

    prep_kernel<<<128, 128>>>(W1, W2, nb);

    int dev = 0;
    cudaGetDevice(&dev);
    int sms = 148;
    cudaDeviceGetAttribute(&sms, cudaDevAttrMultiProcessorCount, dev);
    const int ntiles = (E + 63) >> 6;
    int grid = sms * 3;
    if (grid > ntiles) grid = ntiles;

    cudaFuncSetAttribute(gs_kernel, cudaFuncAttributeMaxDynamicSharedMemorySize, SMEM_TOTAL);
    gs_kernel<<<grid, 256, SMEM_TOTAL>>>(x, nb, b1, b2, out, E);
}

// round 4
// speedup vs baseline: 1.2925x; 1.2925x over previous
#include <cuda_runtime.h>
#include <cuda_bf16.h>
#include <cstdint>

#define DINL __device__ __forceinline__

// ======================= helpers =======================
DINL uint32_t smem_u32(const void* p) {
    uint32_t a;
    asm("{ .reg .u64 t; cvta.to.shared.u64 t, %1; cvt.u32.u64 %0, t; }" : "=r"(a) : "l"(p));
    return a;
}
DINL void ldsm_x4(uint32_t r[4], uint32_t addr) {
    asm volatile("ldmatrix.sync.aligned.m8n8.x4.shared.b16 {%0,%1,%2,%3}, [%4];"
        : "=r"(r[0]), "=r"(r[1]), "=r"(r[2]), "=r"(r[3]) : "r"(addr));
}
DINL void mma_bf16(float c[4], const uint32_t a[4], const uint32_t b[2]) {
    asm volatile("mma.sync.aligned.m16n8k16.row.col.f32.bf16.bf16.f32 "
        "{%0,%1,%2,%3}, {%4,%5,%6,%7}, {%8,%9}, {%0,%1,%2,%3};"
        : "+f"(c[0]), "+f"(c[1]), "+f"(c[2]), "+f"(c[3])
        : "r"(a[0]), "r"(a[1]), "r"(a[2]), "r"(a[3]), "r"(b[0]), "r"(b[1]));
}
#define STS32(a, v) asm volatile("st.shared.b32 [%0], %1;" :: "r"(a), "r"(v) : "memory")
#define STS64(a, v) asm volatile("st.shared.b64 [%0], %1;" :: "r"(a), "l"(v) : "memory")

DINL uint32_t pack2(float a, float b) {
    return ((uint32_t)__bfloat16_as_ushort(__float2bfloat16(b)) << 16)
         |  (uint32_t)__bfloat16_as_ushort(__float2bfloat16(a));
}
DINL uint64_t pack4(float a, float b, float c, float d) {
    return ((uint64_t)pack2(c, d) << 32) | (uint64_t)pack2(a, b);
}
DINL float rlo(float f) { return f - __bfloat162float(__float2bfloat16(f)); }

// ======================= SMEM layout =======================
// A0 hi [0,8K) lo [8K,16K) | A1 hi [16K,24K) lo [24K,32K) | h hi [32K,40K) lo [40K,48K)
static constexpr int SMEM_TOTAL = 49152;

// ======================= device globals =======================
__device__ __align__(16) unsigned char g_wimg[4 * 32768];  // [n][k] bf16: W1h W1l W2h W2l
__device__ int g_idx64;
static constexpr int IDX_CAP = 1 << 20;
__device__ int g_idxp[IDX_CAP];  // precomputed row offsets (idx*128)

// ======================= prologues =======================
__global__ void prep_w(const float* __restrict__ W1, const float* __restrict__ W2,
                       const void* __restrict__ nbr_raw) {
    int n = blockIdx.x, k = threadIdx.x;
    float w1e = W1[k * 128 + n] + W1[(k + 128) * 128 + n];  // fold concat
    float w2v = W2[k * 128 + n];
    __nv_bfloat16* img = (__nv_bfloat16*)g_wimg;
    __nv_bfloat16 h1 = __float2bfloat16(w1e);
    __nv_bfloat16 l1 = __float2bfloat16(w1e - __bfloat162float(h1));
    __nv_bfloat16 h2 = __float2bfloat16(w2v);
    __nv_bfloat16 l2 = __float2bfloat16(w2v - __bfloat162float(h2));
    img[0 * 16384 + n * 128 + k] = h1;
    img[1 * 16384 + n * 128 + k] = l1;
    img[2 * 16384 + n * 128 + k] = h2;
    img[3 * 16384 + n * 128 + k] = l2;
    if (blockIdx.x == 0 && threadIdx.x == 0) {
        const unsigned* w = (const unsigned*)nbr_raw;
        int is64 = 1;
        for (int i = 0; i < 64; i++)
            if (w[2 * i + 1] != 0u) { is64 = 0; break; }
        g_idx64 = is64;
    }
}

__global__ void prep_idx(const void* __restrict__ nbr_raw, int E) {
    int i = blockIdx.x * 256 + threadIdx.x;
    if (i >= E || i >= IDX_CAP) return;
    long long v = g_idx64 ? ((const long long*)nbr_raw)[i]
                          : (long long)((const int*)nbr_raw)[i];
    g_idxp[i] = ((int)v) << 7;  // * 128 floats per row
}

// ======================= main kernel =======================
__global__ void __launch_bounds__(512, 1)
gs_kernel(const float* __restrict__ x,
          const float* __restrict__ b1, const float* __restrict__ b2,
          float* __restrict__ out, int E) {
    extern __shared__ unsigned char sm[];
    const uint32_t sb = smem_u32(sm);
    const int tid = threadIdx.x, wid = tid >> 5, lane = tid & 31;

    // ---- persistent B fragments (this warp's 8 output cols, both GEMMs, hi/lo) ----
    uint32_t B1h[8][2], B1l[8][2], B2h[8][2], B2l[8][2];
    {
        const uint32_t* w32 = (const uint32_t*)g_wimg;
        const int nb = (wid * 8 + (lane >> 2)) * 64;
        const int lc = lane & 3;
#pragma unroll
        for (int ks = 0; ks < 8; ks++)
#pragma unroll
            for (int j = 0; j < 2; j++) {
                const int wi = nb + ks * 8 + j * 4 + lc;
                B1h[ks][j] = w32[wi];
                B1l[ks][j] = w32[8192 + wi];
                B2h[ks][j] = w32[16384 + wi];
                B2l[ks][j] = w32[24576 + wi];
            }
    }
    const int n0 = wid * 8 + (lane & 3) * 2;
    const float b1a = b1[n0], b1b = b1[n0 + 1];
    const float b2a = b2[n0], b2b = b2[n0 + 1];

    // ldmatrix lane addressing for A/h fragments
    const int li = lane & 7, lg = lane >> 3;
    const int arow = ((lg & 1) << 3) + li;
    const int akh = lg >> 1;
    const uint32_t arowoff = (uint32_t)arow * 256u;
    const int arx = arow & 7;

    const uint32_t H_HI = sb + 32768u, H_LO = sb + 40960u;

    const int ntiles = (E + 31) >> 5;
    const int stride = gridDim.x;
    int tile = blockIdx.x;
    if (tile >= ntiles) return;

    // gather lane/store precompute
    const uint32_t gwithin = (uint32_t)((lane & 1) << 3);
    const int gc = lane >> 1;

    // ---- initial gather: tile -> buffer 0 ----
    {
        const int gr = (tile << 5) + wid * 2;
        const int o0 = (gr < E) ? g_idxp[gr] : 0;
        const int o1 = (gr + 1 < E) ? g_idxp[gr + 1] : 0;
        const float4 v0 = *(const float4*)(x + o0 + (lane << 2));
        const float4 v1 = *(const float4*)(x + o1 + (lane << 2));
        const int r0 = wid * 2, r1 = r0 + 1;
        const uint32_t a0 = (uint32_t)(r0 * 256) + (uint32_t)((gc ^ (r0 & 7)) << 4) + gwithin;
        const uint32_t a1 = (uint32_t)(r1 * 256) + (uint32_t)((gc ^ (r1 & 7)) << 4) + gwithin;
        STS64(sb + a0, pack4(v0.x, v0.y, v0.z, v0.w));
        STS64(sb + 8192u + a0, pack4(rlo(v0.x), rlo(v0.y), rlo(v0.z), rlo(v0.w)));
        STS64(sb + a1, pack4(v1.x, v1.y, v1.z, v1.w));
        STS64(sb + 8192u + a1, pack4(rlo(v1.x), rlo(v1.y), rlo(v1.z), rlo(v1.w)));
    }
    __syncthreads();

    uint32_t cur = 0;
    for (; tile < ntiles; tile += stride) {
        const int rowbase = tile << 5;
        const uint32_t A_HI = sb + cur * 16384u, A_LO = A_HI + 8192u;

        // ================= GEMM1: h = relu(A @ W1eff + b1) =================
#pragma unroll
        for (int mt = 0; mt < 2; mt++) {
            float accA[4] = {0.f, 0.f, 0.f, 0.f}, accB[4] = {0.f, 0.f, 0.f, 0.f};
            const uint32_t mtoff = (uint32_t)(mt * 4096);
#pragma unroll
            for (int kq = 0; kq < 4; kq++) {
                uint32_t Ah[2][4], Al[2][4];
#pragma unroll
                for (int k2 = 0; k2 < 2; k2++) {
                    const int ks = kq * 2 + k2;
                    const uint32_t c = (uint32_t)((((ks << 1) + akh) ^ arx) << 4);
                    ldsm_x4(Ah[k2], A_HI + mtoff + arowoff + c);
                    ldsm_x4(Al[k2], A_LO + mtoff + arowoff + c);
                }
#pragma unroll
                for (int k2 = 0; k2 < 2; k2++) {
                    const int ks = kq * 2 + k2;
                    mma_bf16(accA, Ah[k2], B1h[ks]);
                    mma_bf16(accB, Ah[k2], B1l[ks]);
                    mma_bf16(accA, Al[k2], B1h[ks]);   // separate chain via accA/accB mix below
                }
            }
            // epilogue -> h hi/lo (swizzled)
            const int r0 = mt * 16 + (lane >> 2), r1 = r0 + 8;
            const float f0 = fmaxf(accA[0] + accB[0] + b1a, 0.f);
            const float f1 = fmaxf(accA[1] + accB[1] + b1b, 0.f);
            const float f2 = fmaxf(accA[2] + accB[2] + b1a, 0.f);
            const float f3 = fmaxf(accA[3] + accB[3] + b1b, 0.f);
            const uint32_t ha0 = (uint32_t)(r0 * 256 + (((n0 >> 3) ^ (r0 & 7)) << 4) + ((n0 & 7) << 1));
            const uint32_t ha1 = (uint32_t)(r1 * 256 + (((n0 >> 3) ^ (r1 & 7)) << 4) + ((n0 & 7) << 1));
            STS32(H_HI + ha0, pack2(f0, f1));
            STS32(H_LO + ha0, pack2(rlo(f0), rlo(f1)));
            STS32(H_HI + ha1, pack2(f2, f3));
            STS32(H_LO + ha1, pack2(rlo(f2), rlo(f3)));
        }
        __syncthreads();   // h ready; A[cur] fully consumed

        // ---- prefetch next tile's gather rows (LDG latency hides under GEMM2 mt=0) ----
        const int nt = tile + stride;
        float4 v0, v1;
        const uint32_t NA_HI = sb + (cur ^ 1u) * 16384u, NA_LO = NA_HI + 8192u;
        if (nt < ntiles) {
            const int gr = (nt << 5) + wid * 2;
            const int o0 = (gr < E) ? g_idxp[gr] : 0;
            const int o1 = (gr + 1 < E) ? g_idxp[gr + 1] : 0;
            v0 = *(const float4*)(x + o0 + (lane << 2));
            v1 = *(const float4*)(x + o1 + (lane << 2));
        }

        // ================= GEMM2: y = h @ W2 + b2 =================
#pragma unroll
        for (int mt = 0; mt < 2; mt++) {
            float accA[4] = {0.f, 0.f, 0.f, 0.f}, accB[4] = {0.f, 0.f, 0.f, 0.f};
            const uint32_t mtoff = (uint32_t)(mt * 4096);
#pragma unroll
            for (int kq = 0; kq < 4; kq++) {
                uint32_t Ah[2][4], Al[2][4];
#pragma unroll
                for (int k2 = 0; k2 < 2; k2++) {
                    const int ks = kq * 2 + k2;
                    const uint32_t c = (uint32_t)((((ks << 1) + akh) ^ arx) << 4);
                    ldsm_x4(Ah[k2], H_HI + mtoff + arowoff + c);
                    ldsm_x4(Al[k2], H_LO + mtoff + arowoff + c);
                }
#pragma unroll
                for (int k2 = 0; k2 < 2; k2++) {
                    const int ks = kq * 2 + k2;
                    mma_bf16(accA, Ah[k2], B2h[ks]);
                    mma_bf16(accB, Ah[k2], B2l[ks]);
                    mma_bf16(accA, Al[k2], B2h[ks]);
                }
            }
            // epilogue -> global
            const int rg0 = rowbase + mt * 16 + (lane >> 2), rg1 = rg0 + 8;
            if (rg0 < E)
                *(float2*)(out + (size_t)rg0 * 128 + n0) =
                    make_float2(accA[0] + accB[0] + b2a, accA[1] + accB[1] + b2b);
            if (rg1 < E)
                *(float2*)(out + (size_t)rg1 * 128 + n0) =
                    make_float2(accA[2] + accB[2] + b2a, accA[3] + accB[3] + b2b);

            // after mt=0's MMA stream, store the gathered rows (LDG done by now)
            if (mt == 0 && nt < ntiles) {
                const int r0 = wid * 2, r1 = r0 + 1;
                const uint32_t a0 = (uint32_t)(r0 * 256) + (uint32_t)((gc ^ (r0 & 7)) << 4) + gwithin;
                const uint32_t a1 = (uint32_t)(r1 * 256) + (uint32_t)((gc ^ (r1 & 7)) << 4) + gwithin;
                STS64(NA_HI + a0, pack4(v0.x, v0.y, v0.z, v0.w));
                STS64(NA_LO + a0, pack4(rlo(v0.x), rlo(v0.y), rlo(v0.z), rlo(v0.w)));
                STS64(NA_HI + a1, pack4(v1.x, v1.y, v1.z, v1.w));
                STS64(NA_LO + a1, pack4(rlo(v1.x), rlo(v1.y), rlo(v1.z), rlo(v1.w)));
            }
        }
        cur ^= 1u;
        __syncthreads();   // h consumed; next A buffer fully written
    }
}

// ======================= launch =======================
extern "C" void kernel_launch(void* const* d_in, const int* in_sizes, int n_in,
                              void* d_out, int out_size) {
    const float* x  = (const float*)d_in[0];
    const void*  nb = d_in[1];
    const float* W1 = (const float*)d_in[2];
    const float* b1 = (const float*)d_in[3];
    const float* W2 = (const float*)d_in[4];
    const float* b2 = (const float*)d_in[5];
    float* out = (float*)d_out;
    const int E = in_sizes[1];

    prep_w<<<128, 128>>>(W1, W2, nb);
    prep_idx<<<(E + 255) / 256, 256>>>(nb, E);

    int dev = 0;
    cudaGetDevice(&dev);
    int sms = 148;
    cudaDeviceGetAttribute(&sms, cudaDevAttrMultiProcessorCount, dev);
    const int ntiles = (E + 31) >> 5;
    int grid = sms;
    if (grid > ntiles) grid = ntiles;

    cudaFuncSetAttribute(gs_kernel, cudaFuncAttributeMaxDynamicSharedMemorySize, SMEM_TOTAL);
    gs_kernel<<<grid, 512, SMEM_TOTAL>>>(x, b1, b2, out, E);
}

// round 5
// speedup vs baseline: 1.4105x; 1.0913x over previous
#include <cuda_runtime.h>
#include <cuda_bf16.h>
#include <cstdint>

#define DINL __device__ __forceinline__

// ======================= helpers =======================
DINL uint32_t smem_u32(const void* p) {
    uint32_t a;
    asm("{ .reg .u64 t; cvta.to.shared.u64 t, %1; cvt.u32.u64 %0, t; }" : "=r"(a) : "l"(p));
    return a;
}
DINL void ldsm_x4(uint32_t r[4], uint32_t addr) {
    asm volatile("ldmatrix.sync.aligned.m8n8.x4.shared.b16 {%0,%1,%2,%3}, [%4];"
        : "=r"(r[0]), "=r"(r[1]), "=r"(r[2]), "=r"(r[3]) : "r"(addr));
}
DINL void ldsm_x2(uint32_t r[2], uint32_t addr) {
    asm volatile("ldmatrix.sync.aligned.m8n8.x2.shared.b16 {%0,%1}, [%2];"
        : "=r"(r[0]), "=r"(r[1]) : "r"(addr));
}
DINL void mma_bf16(float c[4], const uint32_t a[4], const uint32_t b[2]) {
    asm volatile("mma.sync.aligned.m16n8k16.row.col.f32.bf16.bf16.f32 "
        "{%0,%1,%2,%3}, {%4,%5,%6,%7}, {%8,%9}, {%0,%1,%2,%3};"
        : "+f"(c[0]), "+f"(c[1]), "+f"(c[2]), "+f"(c[3])
        : "r"(a[0]), "r"(a[1]), "r"(a[2]), "r"(a[3]), "r"(b[0]), "r"(b[1]));
}
#define STS32(a, v) asm volatile("st.shared.b32 [%0], %1;" :: "r"(a), "r"(v) : "memory")
#define STS64(a, v) asm volatile("st.shared.b64 [%0], %1;" :: "r"(a), "l"(v) : "memory")

DINL uint32_t pack2(float a, float b) {
    return ((uint32_t)__bfloat16_as_ushort(__float2bfloat16(b)) << 16)
         |  (uint32_t)__bfloat16_as_ushort(__float2bfloat16(a));
}
DINL uint64_t pack4(float a, float b, float c, float d) {
    return ((uint64_t)pack2(c, d) << 32) | (uint64_t)pack2(a, b);
}
DINL float rlo(float f) { return f - __bfloat162float(__float2bfloat16(f)); }

// ======================= SMEM layout =======================
// A0 hi[0,8K) lo[8K,16K) | A1 hi[16K,24K) lo[24K,32K) | H hi[32K,40K) lo[40K,48K)
// W1lo tile [48K,80K) | W2lo tile [80K,112K)
static constexpr int OFF_H   = 32768;
static constexpr int OFF_W1L = 49152;
static constexpr int OFF_W2L = 81920;
static constexpr int SMEM_TOTAL = 114688;

// ======================= device globals =======================
__device__ __align__(16) uint32_t g_whi[2][8192];        // plain [n][kword] bf16x2: W1h, W2h
__device__ __align__(16) unsigned char g_wlo[2][32768];  // swizzled [n][k] tiles: W1l, W2l
__device__ int g_idx64;
static constexpr int IDX_CAP = 1 << 20;
__device__ int g_idxp[IDX_CAP];

// ======================= prologues =======================
__global__ void prep_w(const float* __restrict__ W1, const float* __restrict__ W2,
                       const void* __restrict__ nbr_raw) {
    int n = blockIdx.x, k = threadIdx.x;
    float w1e = W1[k * 128 + n] + W1[(k + 128) * 128 + n];  // fold concat
    float w2v = W2[k * 128 + n];
    __nv_bfloat16 h1 = __float2bfloat16(w1e);
    __nv_bfloat16 l1 = __float2bfloat16(w1e - __bfloat162float(h1));
    __nv_bfloat16 h2 = __float2bfloat16(w2v);
    __nv_bfloat16 l2 = __float2bfloat16(w2v - __bfloat162float(h2));
    ((__nv_bfloat16*)g_whi[0])[n * 128 + k] = h1;
    ((__nv_bfloat16*)g_whi[1])[n * 128 + k] = h2;
    uint32_t ta = (uint32_t)(n * 256 + (((k >> 3) ^ (n & 7)) << 4) + ((k & 7) << 1));
    *(__nv_bfloat16*)(g_wlo[0] + ta) = l1;
    *(__nv_bfloat16*)(g_wlo[1] + ta) = l2;
    if (blockIdx.x == 0 && threadIdx.x == 0) {
        const unsigned* w = (const unsigned*)nbr_raw;
        int is64 = 1;
        for (int i = 0; i < 64; i++)
            if (w[2 * i + 1] != 0u) { is64 = 0; break; }
        g_idx64 = is64;
    }
}

__global__ void prep_idx(const void* __restrict__ nbr_raw, int E) {
    int i = blockIdx.x * 256 + threadIdx.x;
    if (i >= E || i >= IDX_CAP) return;
    long long v = g_idx64 ? ((const long long*)nbr_raw)[i]
                          : (long long)((const int*)nbr_raw)[i];
    g_idxp[i] = ((int)v) << 7;
}

// ======================= main kernel =======================
__global__ void __launch_bounds__(512, 1)
gs_kernel(const float* __restrict__ x,
          const float* __restrict__ b1, const float* __restrict__ b2,
          float* __restrict__ out, int E) {
    extern __shared__ unsigned char sm[];
    const uint32_t sb = smem_u32(sm);
    const int tid = threadIdx.x, wid = tid >> 5, lane = tid & 31;
    const int mg = wid >> 3, ng = wid & 7;          // 2 M-groups x 8 N-groups

    // ---- copy W-lo tiles to SMEM (64KB) ----
    {
        const uint4* s = (const uint4*)g_wlo;
        uint4* d = (uint4*)(sm + OFF_W1L);
#pragma unroll
        for (int i = tid; i < 65536 / 16; i += 512) d[i] = s[i];
    }

    // ---- persistent B-hi fragments: this warp's 16 cols, both GEMMs ----
    uint32_t B1h[2][8][2], B2h[2][8][2];   // [n8 chunk][ks][j]
    {
        const int lc = lane & 3;
#pragma unroll
        for (int ch = 0; ch < 2; ch++) {
            const int nb = (ng * 16 + ch * 8 + (lane >> 2)) * 64;
#pragma unroll
            for (int ks = 0; ks < 8; ks++)
#pragma unroll
                for (int j = 0; j < 2; j++) {
                    const int wi = nb + ks * 8 + j * 4 + lc;
                    B1h[ch][ks][j] = g_whi[0][wi];
                    B2h[ch][ks][j] = g_whi[1][wi];
                }
        }
    }
    float b1r[2][2], b2r[2][2];
#pragma unroll
    for (int ch = 0; ch < 2; ch++) {
        const int n0 = ng * 16 + ch * 8 + (lane & 3) * 2;
        b1r[ch][0] = b1[n0]; b1r[ch][1] = b1[n0 + 1];
        b2r[ch][0] = b2[n0]; b2r[ch][1] = b2[n0 + 1];
    }

    // ldmatrix lane addressing
    const int li = lane & 7, lg = lane >> 3;
    const int arow = ((lg & 1) << 3) + li;          // A row within 16
    const int akh = lg >> 1;                        // k half
    const uint32_t aoff = (uint32_t)(mg * 4096 + arow * 256);
    const int arx = arow & 7;
    const int bg = lg & 1;                          // B x2 k-half select (lanes 0-15)
    const uint32_t bl_row0 = (uint32_t)((ng * 16 + li) * 256);       // chunk 0
    const uint32_t bl_row1 = (uint32_t)((ng * 16 + 8 + li) * 256);   // chunk 1
    const int blx0 = (ng * 16 + li) & 7, blx1 = (ng * 16 + 8 + li) & 7;

    const uint32_t H_HI = sb + OFF_H, H_LO = H_HI + 8192u;
    const uint32_t W1L = sb + OFF_W1L, W2L = sb + OFF_W2L;

    const int ntiles = (E + 31) >> 5;
    const int stride = gridDim.x;
    int tile = blockIdx.x;
    if (tile >= ntiles) return;

    // gather store precompute
    const uint32_t gwithin = (uint32_t)((lane & 1) << 3);
    const int gc = lane >> 1;
    const int gr_base = wid * 2;

    // ---- initial gather into buffer 0 ----
    {
        const int gr = (tile << 5) + gr_base;
        const int o0 = (gr < E) ? g_idxp[gr] : 0;
        const int o1 = (gr + 1 < E) ? g_idxp[gr + 1] : 0;
        const float4 v0 = *(const float4*)(x + o0 + (lane << 2));
        const float4 v1 = *(const float4*)(x + o1 + (lane << 2));
        const int r0 = gr_base, r1 = r0 + 1;
        const uint32_t a0 = (uint32_t)(r0 * 256) + (uint32_t)((gc ^ (r0 & 7)) << 4) + gwithin;
        const uint32_t a1 = (uint32_t)(r1 * 256) + (uint32_t)((gc ^ (r1 & 7)) << 4) + gwithin;
        STS64(sb + a0, pack4(v0.x, v0.y, v0.z, v0.w));
        STS64(sb + 8192u + a0, pack4(rlo(v0.x), rlo(v0.y), rlo(v0.z), rlo(v0.w)));
        STS64(sb + a1, pack4(v1.x, v1.y, v1.z, v1.w));
        STS64(sb + 8192u + a1, pack4(rlo(v1.x), rlo(v1.y), rlo(v1.z), rlo(v1.w)));
    }
    __syncthreads();

    uint32_t cur = 0;
    for (; tile < ntiles; tile += stride) {
        const int rowbase = tile << 5;
        const uint32_t A_HI = sb + cur * 16384u, A_LO = A_HI + 8192u;

        // ================= GEMM1: h = relu(A @ W1eff + b1) =================
        float acc[2][4] = {{0.f,0.f,0.f,0.f},{0.f,0.f,0.f,0.f}};
#pragma unroll
        for (int kq = 0; kq < 4; kq++) {
            uint32_t Ah[2][4], Al[2][4], Bl[2][2][2];
#pragma unroll
            for (int k2 = 0; k2 < 2; k2++) {
                const int ks = kq * 2 + k2;
                const uint32_t c = (uint32_t)((((ks << 1) + akh) ^ arx) << 4);
                ldsm_x4(Ah[k2], A_HI + aoff + c);
                ldsm_x4(Al[k2], A_LO + aoff + c);
                ldsm_x2(Bl[k2][0], W1L + bl_row0 + (uint32_t)((((ks << 1) + bg) ^ blx0) << 4));
                ldsm_x2(Bl[k2][1], W1L + bl_row1 + (uint32_t)((((ks << 1) + bg) ^ blx1) << 4));
            }
#pragma unroll
            for (int k2 = 0; k2 < 2; k2++) {
                const int ks = kq * 2 + k2;
                mma_bf16(acc[0], Ah[k2], B1h[0][ks]);
                mma_bf16(acc[1], Ah[k2], B1h[1][ks]);
                mma_bf16(acc[0], Ah[k2], Bl[k2][0]);
                mma_bf16(acc[1], Ah[k2], Bl[k2][1]);
                mma_bf16(acc[0], Al[k2], B1h[0][ks]);
                mma_bf16(acc[1], Al[k2], B1h[1][ks]);
            }
        }
        // epilogue -> h hi/lo (swizzled)
        {
            const int r0 = mg * 16 + (lane >> 2), r1 = r0 + 8;
#pragma unroll
            for (int ch = 0; ch < 2; ch++) {
                const float f0 = fmaxf(acc[ch][0] + b1r[ch][0], 0.f);
                const float f1 = fmaxf(acc[ch][1] + b1r[ch][1], 0.f);
                const float f2 = fmaxf(acc[ch][2] + b1r[ch][0], 0.f);
                const float f3 = fmaxf(acc[ch][3] + b1r[ch][1], 0.f);
                const int col = ng * 16 + ch * 8 + (lane & 3) * 2;
                const uint32_t u = (uint32_t)((col >> 3) & 15);
                const uint32_t w0 = (uint32_t)((col & 7) << 1);
                const uint32_t ha0 = (uint32_t)(r0 * 256) + (uint32_t)(((u ^ (r0 & 7))) << 4) + w0;
                const uint32_t ha1 = (uint32_t)(r1 * 256) + (uint32_t)(((u ^ (r1 & 7))) << 4) + w0;
                STS32(H_HI + ha0, pack2(f0, f1));
                STS32(H_LO + ha0, pack2(rlo(f0), rlo(f1)));
                STS32(H_HI + ha1, pack2(f2, f3));
                STS32(H_LO + ha1, pack2(rlo(f2), rlo(f3)));
            }
        }
        __syncthreads();   // h ready; A[cur] consumed

        // ---- prefetch next tile's rows (LDG hides under GEMM2) ----
        const int nt = tile + stride;
        float4 v0, v1;
        if (nt < ntiles) {
            const int gr = (nt << 5) + gr_base;
            const int o0 = (gr < E) ? g_idxp[gr] : 0;
            const int o1 = (gr + 1 < E) ? g_idxp[gr + 1] : 0;
            v0 = *(const float4*)(x + o0 + (lane << 2));
            v1 = *(const float4*)(x + o1 + (lane << 2));
        }

        // ================= GEMM2: y = h @ W2 + b2 =================
        float acc2[2][4] = {{0.f,0.f,0.f,0.f},{0.f,0.f,0.f,0.f}};
#pragma unroll
        for (int kq = 0; kq < 4; kq++) {
            uint32_t Ah[2][4], Al[2][4], Bl[2][2][2];
#pragma unroll
            for (int k2 = 0; k2 < 2; k2++) {
                const int ks = kq * 2 + k2;
                const uint32_t c = (uint32_t)((((ks << 1) + akh) ^ arx) << 4);
                ldsm_x4(Ah[k2], H_HI + aoff + c);
                ldsm_x4(Al[k2], H_LO + aoff + c);
                ldsm_x2(Bl[k2][0], W2L + bl_row0 + (uint32_t)((((ks << 1) + bg) ^ blx0) << 4));
                ldsm_x2(Bl[k2][1], W2L + bl_row1 + (uint32_t)((((ks << 1) + bg) ^ blx1) << 4));
            }
#pragma unroll
            for (int k2 = 0; k2 < 2; k2++) {
                const int ks = kq * 2 + k2;
                mma_bf16(acc2[0], Ah[k2], B2h[0][ks]);
                mma_bf16(acc2[1], Ah[k2], B2h[1][ks]);
                mma_bf16(acc2[0], Ah[k2], Bl[k2][0]);
                mma_bf16(acc2[1], Ah[k2], Bl[k2][1]);
                mma_bf16(acc2[0], Al[k2], B2h[0][ks]);
                mma_bf16(acc2[1], Al[k2], B2h[1][ks]);
            }
        }

        // ---- store gathered rows into other A buffer ----
        if (nt < ntiles) {
            const uint32_t NA_HI = sb + (cur ^ 1u) * 16384u, NA_LO = NA_HI + 8192u;
            const int r0 = gr_base, r1 = r0 + 1;
            const uint32_t a0 = (uint32_t)(r0 * 256) + (uint32_t)((gc ^ (r0 & 7)) << 4) + gwithin;
            const uint32_t a1 = (uint32_t)(r1 * 256) + (uint32_t)((gc ^ (r1 & 7)) << 4) + gwithin;
            STS64(NA_HI + a0, pack4(v0.x, v0.y, v0.z, v0.w));
            STS64(NA_LO + a0, pack4(rlo(v0.x), rlo(v0.y), rlo(v0.z), rlo(v0.w)));
            STS64(NA_HI + a1, pack4(v1.x, v1.y, v1.z, v1.w));
            STS64(NA_LO + a1, pack4(rlo(v1.x), rlo(v1.y), rlo(v1.z), rlo(v1.w)));
        }

        // ---- epilogue -> global ----
        {
            const int rg0 = rowbase + mg * 16 + (lane >> 2), rg1 = rg0 + 8;
#pragma unroll
            for (int ch = 0; ch < 2; ch++) {
                const int col = ng * 16 + ch * 8 + (lane & 3) * 2;
                if (rg0 < E)
                    *(float2*)(out + (size_t)rg0 * 128 + col) =
                        make_float2(acc2[ch][0] + b2r[ch][0], acc2[ch][1] + b2r[ch][1]);
                if (rg1 < E)
                    *(float2*)(out + (size_t)rg1 * 128 + col) =
                        make_float2(acc2[ch][2] + b2r[ch][0], acc2[ch][3] + b2r[ch][1]);
            }
        }
        cur ^= 1u;
        __syncthreads();   // h consumed; next A buffer complete
    }
}

// ======================= launch =======================
extern "C" void kernel_launch(void* const* d_in, const int* in_sizes, int n_in,
                              void* d_out, int out_size) {
    const float* x  = (const float*)d_in[0];
    const void*  nb = d_in[1];
    const float* W1 = (const float*)d_in[2];
    const float* b1 = (const float*)d_in[3];
    const float* W2 = (const float*)d_in[4];
    const float* b2 = (const float*)d_in[5];
    float* out = (float*)d_out;
    const int E = in_sizes[1];

    prep_w<<<128, 128>>>(W1, W2, nb);
    prep_idx<<<(E + 255) / 256, 256>>>(nb, E);

    int dev = 0;
    cudaGetDevice(&dev);
    int sms = 148;
    cudaDeviceGetAttribute(&sms, cudaDevAttrMultiProcessorCount, dev);
    const int ntiles = (E + 31) >> 5;
    int grid = sms;
    if (grid > ntiles) grid = ntiles;

    cudaFuncSetAttribute(gs_kernel, cudaFuncAttributeMaxDynamicSharedMemorySize, SMEM_TOTAL);
    gs_kernel<<<grid, 512, SMEM_TOTAL>>>(x, b1, b2, out, E);
}